// round 14
// baseline (speedup 1.0000x reference)
#include <cuda_runtime.h>
#include <cuda_fp16.h>
#include <cstdint>

#define N_NODES 100000
#define E_EDGES 1600000
#define DIM 128
#define FULL 0xffffffffu
#define SCAN_BLOCKS 98   // 98 * 1024 >= N_NODES

// ------------------------- device scratch (no allocs) ----------------------
__device__ __half g_h[(size_t)N_NODES * DIM];    // ori = x@W^T + b (fp16)
__device__ __half g_t[(size_t)N_NODES * DIM];    // relu(ln0(h)), fp16
__device__ __half g_t2[(size_t)N_NODES * DIM];   // relu(ln1(agg0+h)), fp16
__device__ int2   g_edge[E_EDGES];               // CSR: (src, w-bits) by dst
__device__ int    g_deg[N_NODES];
__device__ int    g_off[N_NODES + 1];
__device__ int    g_cursor[N_NODES];
__device__ int    g_bsum[128];
__device__ int    g_is64;

// ---- f32x2 packed helpers (sm_103a FFMA2 path) ----------------------------
__device__ __forceinline__ unsigned long long pack2(float a, float b) {
    unsigned long long r;
    asm("mov.b64 %0, {%1, %2};" : "=l"(r) : "f"(a), "f"(b));
    return r;
}
__device__ __forceinline__ void fma2(unsigned long long& d,
                                     unsigned long long a,
                                     unsigned long long b) {
    asm("fma.rn.f32x2 %0, %1, %2, %0;" : "+l"(d) : "l"(a), "l"(b));
}
__device__ __forceinline__ float2 unpack2(unsigned long long v) {
    float2 r;
    asm("mov.b64 {%0, %1}, %2;" : "=f"(r.x), "=f"(r.y) : "l"(v));
    return r;
}

// ---- zero degrees + detect int64 layout (fused) ---------------------------
__global__ void zero_detect_kernel(const int* __restrict__ raw) {
    int i = blockIdx.x * blockDim.x + threadIdx.x;
    if (i < N_NODES) g_deg[i] = 0;
    if (blockIdx.x == 0 && threadIdx.x < 32) {
        int lane = threadIdx.x;
        int nz = 0;
        if (raw[2 * (2 * lane + 0) + 1] != 0) nz = 1;
        if (raw[2 * (2 * lane + 1) + 1] != 0) nz = 1;
        unsigned m = __ballot_sync(FULL, nz);
        if (lane == 0) g_is64 = (m == 0u) ? 1 : 0;
    }
}

// ---- histogram dst degrees, 2 edges/thread (independent REDs) -------------
__global__ void hist_kernel(const int* __restrict__ raw) {
    int tp = blockIdx.x * blockDim.x + threadIdx.x;
    if (tp * 2 >= E_EDGES) return;
    int d0, d1;
    if (g_is64) {
        int4 v = __ldg((const int4*)(raw + 2 * (size_t)E_EDGES) + tp);
        d0 = v.x; d1 = v.z;
    } else {
        int2 v = __ldg((const int2*)(raw + E_EDGES) + tp);
        d0 = v.x; d1 = v.y;
    }
    d0 = min(max(d0, 0), N_NODES - 1);
    d1 = min(max(d1, 0), N_NODES - 1);
    atomicAdd(&g_deg[d0], 1);   // E_EDGES is even: both edges always valid
    atomicAdd(&g_deg[d1], 1);
}

// ---- parallel scan, phase 1: per-block sums -------------------------------
__global__ void block_sum_kernel() {
    __shared__ int ws[32];
    int tid = threadIdx.x, lane = tid & 31, wid = tid >> 5;
    int idx = blockIdx.x * 1024 + tid;
    int v = (idx < N_NODES) ? g_deg[idx] : 0;
#pragma unroll
    for (int o = 16; o; o >>= 1) v += __shfl_xor_sync(FULL, v, o);
    if (lane == 0) ws[wid] = v;
    __syncthreads();
    if (wid == 0) {
        int s = ws[lane];
#pragma unroll
        for (int o = 16; o; o >>= 1) s += __shfl_xor_sync(FULL, s, o);
        if (lane == 0) g_bsum[blockIdx.x] = s;
    }
}

// ---- scan phase 2+3 fused (race-free cross-warp fixup) --------------------
__global__ void scan_apply_kernel() {
    __shared__ int wsum[32];
    __shared__ int sb[128];
    __shared__ int wtot[4];
    int tid = threadIdx.x, lane = tid & 31, wid = tid >> 5;

    int bs_incl = 0;
    if (tid < 128) {
        int v = (tid < SCAN_BLOCKS) ? g_bsum[tid] : 0;
        bs_incl = v;
#pragma unroll
        for (int o = 1; o < 32; o <<= 1) {
            int n = __shfl_up_sync(FULL, bs_incl, o);
            if (lane >= o) bs_incl += n;
        }
        if (lane == 31) wtot[wid] = bs_incl;
    }
    __syncthreads();
    if (tid < 128) {
        int base = 0;
#pragma unroll
        for (int w = 0; w < 4; w++)
            if (w < wid) base += wtot[w];
        sb[tid] = bs_incl + base;
    }
    __syncthreads();
    int myBase = (blockIdx.x == 0) ? 0 : sb[blockIdx.x - 1];

    int idx = blockIdx.x * 1024 + tid;
    int v = (idx < N_NODES) ? g_deg[idx] : 0;
    int inc = v;
#pragma unroll
    for (int o = 1; o < 32; o <<= 1) {
        int n = __shfl_up_sync(FULL, inc, o);
        if (lane >= o) inc += n;
    }
    if (lane == 31) wsum[wid] = inc;
    __syncthreads();
    if (wid == 0) {
        int w = wsum[lane];
        int wi = w;
#pragma unroll
        for (int o = 1; o < 32; o <<= 1) {
            int n = __shfl_up_sync(FULL, wi, o);
            if (lane >= o) wi += n;
        }
        wsum[lane] = wi - w;
    }
    __syncthreads();
    int excl = myBase + wsum[wid] + (inc - v);
    if (idx < N_NODES) { g_off[idx] = excl; g_cursor[idx] = excl; }
    if (idx == 0) g_off[N_NODES] = E_EDGES;
}

// ---- fill CSR buckets, 2 edges/thread -------------------------------------
__global__ void fill_kernel(const int* __restrict__ raw,
                            const float* __restrict__ ef) {
    int tp = blockIdx.x * blockDim.x + threadIdx.x;
    if (tp * 2 >= E_EDGES) return;
    int s0, s1, d0, d1;
    if (g_is64) {
        int4 sv = __ldg((const int4*)raw + tp);
        int4 dv = __ldg((const int4*)(raw + 2 * (size_t)E_EDGES) + tp);
        s0 = sv.x; s1 = sv.z; d0 = dv.x; d1 = dv.z;
    } else {
        int2 sv = __ldg((const int2*)raw + tp);
        int2 dv = __ldg((const int2*)(raw + E_EDGES) + tp);
        s0 = sv.x; s1 = sv.y; d0 = dv.x; d1 = dv.y;
    }
    float2 wv = __ldg((const float2*)ef + tp);
    s0 = min(max(s0, 0), N_NODES - 1);
    d0 = min(max(d0, 0), N_NODES - 1);
    s1 = min(max(s1, 0), N_NODES - 1);
    d1 = min(max(d1, 0), N_NODES - 1);
    int p0 = atomicAdd(&g_cursor[d0], 1);
    int p1 = atomicAdd(&g_cursor[d1], 1);
    if (p0 >= 0 && p0 < E_EDGES) g_edge[p0] = make_int2(s0, __float_as_int(wv.x));
    if (p1 >= 0 && p1 < E_EDGES) g_edge[p1] = make_int2(s1, __float_as_int(wv.y));
}

// ---- GEMM (h = x @ W^T + b) fused with LN0 + ReLU, f32x2 FMA --------------
#define WS_PITCH 132
__global__ void gemm_ln_kernel(const float* __restrict__ x,
                               const float* __restrict__ W,
                               const float* __restrict__ b,
                               const float* __restrict__ scale,
                               const float* __restrict__ bias,
                               __half* __restrict__ h_out,
                               __half* __restrict__ t_out) {
    extern __shared__ float4 smem[];
    float4* Ws = smem;                      // [k4][col] pitch WS_PITCH
    float4* Xs = smem + 32 * WS_PITCH;      // [warp*8 + r][k4]

    int tid = threadIdx.x, lane = tid & 31, warp = tid >> 5;
    int rowBase = blockIdx.x * 64 + warp * 8;

    for (int idx = tid; idx < DIM * 32; idx += 256) {
        int col = idx >> 5, k4 = idx & 31;
        Ws[k4 * WS_PITCH + col] = ((const float4*)W)[idx];
    }
    for (int r = 0; r < 8; r++) {
        int row = rowBase + r;
        float4 v = make_float4(0.f, 0.f, 0.f, 0.f);
        if (row < N_NODES) v = ((const float4*)x)[(size_t)row * 32 + lane];
        Xs[(warp * 8 + r) * 32 + lane] = v;
    }
    __syncthreads();

    unsigned long long acc2[8][4];
#pragma unroll
    for (int r = 0; r < 8; r++)
#pragma unroll
        for (int c = 0; c < 4; c++) acc2[r][c] = 0ull;

    for (int k4 = 0; k4 < 32; k4++) {
        unsigned long long xa[8], xb[8];
#pragma unroll
        for (int r = 0; r < 8; r++) {
            float4 xv = Xs[(warp * 8 + r) * 32 + k4];
            xa[r] = pack2(xv.x, xv.y);
            xb[r] = pack2(xv.z, xv.w);
        }
#pragma unroll
        for (int c = 0; c < 4; c++) {
            float4 wv = Ws[k4 * WS_PITCH + c * 32 + lane];
            unsigned long long wa = pack2(wv.x, wv.y);
            unsigned long long wb = pack2(wv.z, wv.w);
#pragma unroll
            for (int r = 0; r < 8; r++) {
                fma2(acc2[r][c], xa[r], wa);
                fma2(acc2[r][c], xb[r], wb);
            }
        }
    }

    float bv[4], sv[4], biv[4];
#pragma unroll
    for (int c = 0; c < 4; c++) {
        bv[c]  = __ldg(b + c * 32 + lane);
        sv[c]  = __ldg(scale + c * 32 + lane);
        biv[c] = __ldg(bias + c * 32 + lane);
    }

#pragma unroll
    for (int r = 0; r < 8; r++) {
        int row = rowBase + r;
        if (row >= N_NODES) break;
        float v[4];
#pragma unroll
        for (int c = 0; c < 4; c++) {
            float2 p = unpack2(acc2[r][c]);
            v[c] = p.x + p.y + bv[c];
        }
        float s = v[0] + v[1] + v[2] + v[3];
#pragma unroll
        for (int o = 16; o; o >>= 1) s += __shfl_xor_sync(FULL, s, o);
        float mu = s * (1.0f / 128.0f);
        float q = 0.f;
#pragma unroll
        for (int c = 0; c < 4; c++) {
            float d = v[c] - mu;
            q += d * d;
        }
#pragma unroll
        for (int o = 16; o; o >>= 1) q += __shfl_xor_sync(FULL, q, o);
        float rstd = rsqrtf(q * (1.0f / 128.0f) + 1e-5f);
        size_t base = (size_t)row * DIM;
#pragma unroll
        for (int c = 0; c < 4; c++) {
            h_out[base + c * 32 + lane] = __float2half_rn(v[c]);
            float t = fmaf((v[c] - mu) * rstd, sv[c], biv[c]);
            t_out[base + c * 32 + lane] = __float2half_rn(fmaxf(t, 0.0f));
        }
    }
}

// ---- CSR aggregation, MLP-12 chunked gathers + tail -----------------------
#define CHUNK 12
template <bool FUSE_LN>
__global__ void agg_kernel(const __half* __restrict__ t,
                           const __half* __restrict__ hres,
                           const float* __restrict__ scale,
                           const float* __restrict__ bias,
                           void* __restrict__ outp) {
    int warp = threadIdx.x >> 5;
    int lane = threadIdx.x & 31;
    int row = blockIdx.x * 8 + warp;
    if (row >= N_NODES) return;

    int beg = g_off[row], end = g_off[row + 1];
    float4 acc = make_float4(0.f, 0.f, 0.f, 0.f);

    int i = beg;
    for (; i + CHUNK <= end; i += CHUNK) {
        int2 eI[CHUNK];
#pragma unroll
        for (int j = 0; j < CHUNK; j++)
            eI[j] = __ldg(g_edge + i + j);     // warp-uniform 8B broadcast
        uint2 rv[CHUNK];
#pragma unroll
        for (int j = 0; j < CHUNK; j++)
            rv[j] = ((const uint2*)(t + (size_t)eI[j].x * DIM))[lane];
#pragma unroll
        for (int j = 0; j < CHUNK; j++) {
            float w = __int_as_float(eI[j].y);
            float2 f0 = __half22float2(*(const __half2*)&rv[j].x);
            float2 f1 = __half22float2(*(const __half2*)&rv[j].y);
            acc.x = fmaf(w, f0.x, acc.x);
            acc.y = fmaf(w, f0.y, acc.y);
            acc.z = fmaf(w, f1.x, acc.z);
            acc.w = fmaf(w, f1.y, acc.w);
        }
    }
    for (; i < end; i++) {
        int2 e = __ldg(g_edge + i);
        float w = __int_as_float(e.y);
        uint2 rv = ((const uint2*)(t + (size_t)e.x * DIM))[lane];
        float2 f0 = __half22float2(*(const __half2*)&rv.x);
        float2 f1 = __half22float2(*(const __half2*)&rv.y);
        acc.x = fmaf(w, f0.x, acc.x);
        acc.y = fmaf(w, f0.y, acc.y);
        acc.z = fmaf(w, f1.x, acc.z);
        acc.w = fmaf(w, f1.y, acc.w);
    }

    size_t base = (size_t)row * DIM;
    if (FUSE_LN) {
        uint2 hv = ((const uint2*)(hres + base))[lane];
        float2 h0 = __half22float2(*(const __half2*)&hv.x);
        float2 h1 = __half22float2(*(const __half2*)&hv.y);
        acc.x += h0.x; acc.y += h0.y; acc.z += h1.x; acc.w += h1.y;
        float s = acc.x + acc.y + acc.z + acc.w;
#pragma unroll
        for (int o2 = 16; o2; o2 >>= 1) s += __shfl_xor_sync(FULL, s, o2);
        float mu = s * (1.0f / 128.0f);
        float dx = acc.x - mu, dy = acc.y - mu, dz = acc.z - mu, dw = acc.w - mu;
        float q = dx * dx + dy * dy + dz * dz + dw * dw;
#pragma unroll
        for (int o2 = 16; o2; o2 >>= 1) q += __shfl_xor_sync(FULL, q, o2);
        float rstd = rsqrtf(q * (1.0f / 128.0f) + 1e-5f);
        float4 sc = ((const float4*)scale)[lane];
        float4 bi = ((const float4*)bias)[lane];
        float rx = fmaxf(fmaf(dx * rstd, sc.x, bi.x), 0.0f);
        float ry = fmaxf(fmaf(dy * rstd, sc.y, bi.y), 0.0f);
        float rz = fmaxf(fmaf(dz * rstd, sc.z, bi.z), 0.0f);
        float rw = fmaxf(fmaf(dw * rstd, sc.w, bi.w), 0.0f);
        uint2 st;
        *(__half2*)&st.x = __floats2half2_rn(rx, ry);
        *(__half2*)&st.y = __floats2half2_rn(rz, rw);
        ((uint2*)((__half*)outp + base))[lane] = st;
    } else {
        ((float4*)((float*)outp + base))[lane] = acc;
    }
}

extern "C" void kernel_launch(void* const* d_in, const int* in_sizes, int n_in,
                              void* d_out, int out_size) {
    const float* x = nullptr;
    const int*   ei_raw = nullptr;
    const float* ef = nullptr;
    const float* lin_w = nullptr;
    const float* lin_b = nullptr;
    const float* ln_scale = nullptr;
    const float* ln_bias = nullptr;
    for (int i = 0; i < n_in; i++) {
        switch (in_sizes[i]) {
            case N_NODES * DIM: x      = (const float*)d_in[i]; break;
            case 2 * E_EDGES:   ei_raw = (const int*)d_in[i];   break;
            case E_EDGES:       ef     = (const float*)d_in[i]; break;
            case DIM * DIM:     lin_w  = (const float*)d_in[i]; break;
            case DIM:           lin_b  = (const float*)d_in[i]; break;
            case 2 * DIM:
                if (!ln_scale) ln_scale = (const float*)d_in[i];
                else           ln_bias  = (const float*)d_in[i];
                break;
            default: break;
        }
    }
    float* out = (float*)d_out;

    __half *h, *t, *t2;
    cudaGetSymbolAddress((void**)&h,  g_h);
    cudaGetSymbolAddress((void**)&t,  g_t);
    cudaGetSymbolAddress((void**)&t2, g_t2);

    const int PAIR_BLKS = ((E_EDGES / 2) + 255) / 256;
    const int NODE_BLKS = (N_NODES + 255) / 256;
    const int ROWS_GRID = (N_NODES + 7) / 8;
    const int GEMM_GRID = (N_NODES + 63) / 64;
    const int GEMM_SMEM = (32 * WS_PITCH + 8 * 8 * 32) * sizeof(float4);

    static cudaStream_t s_side = nullptr;
    static cudaEvent_t  ev_fork = nullptr, ev_join = nullptr;
    static bool init_done = false;
    if (!init_done) {
        cudaFuncSetAttribute(gemm_ln_kernel,
                             cudaFuncAttributeMaxDynamicSharedMemorySize,
                             GEMM_SMEM);
        if (cudaStreamCreateWithFlags(&s_side, cudaStreamNonBlocking) !=
            cudaSuccess) s_side = nullptr;
        if (s_side) {
            cudaEventCreateWithFlags(&ev_fork, cudaEventDisableTiming);
            cudaEventCreateWithFlags(&ev_join, cudaEventDisableTiming);
        }
        init_done = true;
    }

    if (s_side) {
        // fork: GEMM+LN0 on side stream, CSR build on main stream
        cudaEventRecord(ev_fork, 0);
        cudaStreamWaitEvent(s_side, ev_fork, 0);
        gemm_ln_kernel<<<GEMM_GRID, 256, GEMM_SMEM, s_side>>>(
            x, lin_w, lin_b, ln_scale, ln_bias, h, t);
        cudaEventRecord(ev_join, s_side);

        zero_detect_kernel<<<NODE_BLKS, 256>>>(ei_raw);
        hist_kernel<<<PAIR_BLKS, 256>>>(ei_raw);
        block_sum_kernel<<<SCAN_BLOCKS, 1024>>>();
        scan_apply_kernel<<<SCAN_BLOCKS, 1024>>>();
        fill_kernel<<<PAIR_BLKS, 256>>>(ei_raw, ef);

        cudaStreamWaitEvent(0, ev_join, 0);   // join before agg0
    } else {
        zero_detect_kernel<<<NODE_BLKS, 256>>>(ei_raw);
        hist_kernel<<<PAIR_BLKS, 256>>>(ei_raw);
        block_sum_kernel<<<SCAN_BLOCKS, 1024>>>();
        scan_apply_kernel<<<SCAN_BLOCKS, 1024>>>();
        fill_kernel<<<PAIR_BLKS, 256>>>(ei_raw, ef);
        gemm_ln_kernel<<<GEMM_GRID, 256, GEMM_SMEM>>>(
            x, lin_w, lin_b, ln_scale, ln_bias, h, t);
    }

    // ---- layer 0 agg + residual + LN1 + ReLU -> t2 (fp16) ----
    agg_kernel<true><<<ROWS_GRID, 256>>>(t, h, ln_scale + DIM, ln_bias + DIM,
                                         (void*)t2);

    // ---- layer 1 agg -> out (fp32) ----
    agg_kernel<false><<<ROWS_GRID, 256>>>(t2, nullptr, nullptr, nullptr,
                                          (void*)out);
}

// round 16
// speedup vs baseline: 1.4631x; 1.4631x over previous
#include <cuda_runtime.h>
#include <cuda_fp16.h>
#include <cstdint>

#define N_NODES 100000
#define E_EDGES 1600000
#define DIM 128
#define FULL 0xffffffffu
#define SCAN_BLOCKS 98   // 98 * 1024 >= N_NODES

// ------------------------- device scratch (no allocs) ----------------------
__device__ __half g_h[(size_t)N_NODES * DIM];    // ori = x@W^T + b (fp16)
__device__ __half g_t[(size_t)N_NODES * DIM];    // relu(ln0(h)), fp16
__device__ __half g_t2[(size_t)N_NODES * DIM];   // relu(ln1(agg0+h)), fp16
__device__ int2   g_edge[E_EDGES];               // CSR: (src, w-bits) by dst
__device__ int    g_deg[N_NODES];
__device__ int    g_off[N_NODES + 1];
__device__ int    g_cursor[N_NODES];
__device__ int    g_bsum[128];
__device__ int    g_is64;

// ---- f32x2 packed helpers (sm_103a FFMA2 path) ----------------------------
__device__ __forceinline__ unsigned long long pack2(float a, float b) {
    unsigned long long r;
    asm("mov.b64 %0, {%1, %2};" : "=l"(r) : "f"(a), "f"(b));
    return r;
}
__device__ __forceinline__ void fma2(unsigned long long& d,
                                     unsigned long long a,
                                     unsigned long long b) {
    asm("fma.rn.f32x2 %0, %1, %2, %0;" : "+l"(d) : "l"(a), "l"(b));
}
__device__ __forceinline__ float2 unpack2(unsigned long long v) {
    float2 r;
    asm("mov.b64 {%0, %1}, %2;" : "=f"(r.x), "=f"(r.y) : "l"(v));
    return r;
}

// ---- zero degrees + detect int64 layout (fused, one launch) ---------------
__global__ void zero_detect_kernel(const int* __restrict__ raw) {
    int i = blockIdx.x * blockDim.x + threadIdx.x;
    if (i < N_NODES) g_deg[i] = 0;
    if (blockIdx.x == 0 && threadIdx.x < 32) {
        int lane = threadIdx.x;
        int nz = 0;
        if (raw[2 * (2 * lane + 0) + 1] != 0) nz = 1;
        if (raw[2 * (2 * lane + 1) + 1] != 0) nz = 1;
        unsigned m = __ballot_sync(FULL, nz);
        if (lane == 0) g_is64 = (m == 0u) ? 1 : 0;
    }
}

// ---- histogram dst degrees (1 edge/thread — proven fastest) ---------------
__global__ void hist_kernel(const int* __restrict__ raw) {
    int e = blockIdx.x * blockDim.x + threadIdx.x;
    if (e >= E_EDGES) return;
    int d = g_is64 ? raw[2 * ((size_t)E_EDGES + e)] : raw[E_EDGES + e];
    d = min(max(d, 0), N_NODES - 1);
    atomicAdd(&g_deg[d], 1);
}

// ---- parallel scan, phase 1: per-block sums -------------------------------
__global__ void block_sum_kernel() {
    __shared__ int ws[32];
    int tid = threadIdx.x, lane = tid & 31, wid = tid >> 5;
    int idx = blockIdx.x * 1024 + tid;
    int v = (idx < N_NODES) ? g_deg[idx] : 0;
#pragma unroll
    for (int o = 16; o; o >>= 1) v += __shfl_xor_sync(FULL, v, o);
    if (lane == 0) ws[wid] = v;
    __syncthreads();
    if (wid == 0) {
        int s = ws[lane];
#pragma unroll
        for (int o = 16; o; o >>= 1) s += __shfl_xor_sync(FULL, s, o);
        if (lane == 0) g_bsum[blockIdx.x] = s;
    }
}

// ---- scan phase 2+3 fused (race-free cross-warp fixup) --------------------
__global__ void scan_apply_kernel() {
    __shared__ int wsum[32];
    __shared__ int sb[128];
    __shared__ int wtot[4];
    int tid = threadIdx.x, lane = tid & 31, wid = tid >> 5;

    int bs_incl = 0;
    if (tid < 128) {
        int v = (tid < SCAN_BLOCKS) ? g_bsum[tid] : 0;
        bs_incl = v;
#pragma unroll
        for (int o = 1; o < 32; o <<= 1) {
            int n = __shfl_up_sync(FULL, bs_incl, o);
            if (lane >= o) bs_incl += n;
        }
        if (lane == 31) wtot[wid] = bs_incl;
    }
    __syncthreads();
    if (tid < 128) {
        int base = 0;
#pragma unroll
        for (int w = 0; w < 4; w++)
            if (w < wid) base += wtot[w];
        sb[tid] = bs_incl + base;
    }
    __syncthreads();
    int myBase = (blockIdx.x == 0) ? 0 : sb[blockIdx.x - 1];

    int idx = blockIdx.x * 1024 + tid;
    int v = (idx < N_NODES) ? g_deg[idx] : 0;
    int inc = v;
#pragma unroll
    for (int o = 1; o < 32; o <<= 1) {
        int n = __shfl_up_sync(FULL, inc, o);
        if (lane >= o) inc += n;
    }
    if (lane == 31) wsum[wid] = inc;
    __syncthreads();
    if (wid == 0) {
        int w = wsum[lane];
        int wi = w;
#pragma unroll
        for (int o = 1; o < 32; o <<= 1) {
            int n = __shfl_up_sync(FULL, wi, o);
            if (lane >= o) wi += n;
        }
        wsum[lane] = wi - w;
    }
    __syncthreads();
    int excl = myBase + wsum[wid] + (inc - v);
    if (idx < N_NODES) { g_off[idx] = excl; g_cursor[idx] = excl; }
    if (idx == 0) g_off[N_NODES] = E_EDGES;
}

// ---- fill CSR buckets (1 edge/thread — proven fastest) --------------------
__global__ void fill_kernel(const int* __restrict__ raw,
                            const float* __restrict__ ef) {
    int e = blockIdx.x * blockDim.x + threadIdx.x;
    if (e >= E_EDGES) return;
    int s, d;
    if (g_is64) {
        s = raw[2 * (size_t)e];
        d = raw[2 * ((size_t)E_EDGES + e)];
    } else {
        s = raw[e];
        d = raw[E_EDGES + e];
    }
    s = min(max(s, 0), N_NODES - 1);
    d = min(max(d, 0), N_NODES - 1);
    int pos = atomicAdd(&g_cursor[d], 1);
    if (pos >= 0 && pos < E_EDGES)                // defensive bound
        g_edge[pos] = make_int2(s, __float_as_int(ef[e]));
}

// ---- GEMM (h = x @ W^T + b) fused with LN0 + ReLU, f32x2 FMA --------------
#define WS_PITCH 132
__global__ void gemm_ln_kernel(const float* __restrict__ x,
                               const float* __restrict__ W,
                               const float* __restrict__ b,
                               const float* __restrict__ scale,
                               const float* __restrict__ bias,
                               __half* __restrict__ h_out,
                               __half* __restrict__ t_out) {
    extern __shared__ float4 smem[];
    float4* Ws = smem;                      // [k4][col] pitch WS_PITCH
    float4* Xs = smem + 32 * WS_PITCH;      // [warp*8 + r][k4]

    int tid = threadIdx.x, lane = tid & 31, warp = tid >> 5;
    int rowBase = blockIdx.x * 64 + warp * 8;

    for (int idx = tid; idx < DIM * 32; idx += 256) {
        int col = idx >> 5, k4 = idx & 31;
        Ws[k4 * WS_PITCH + col] = ((const float4*)W)[idx];
    }
    for (int r = 0; r < 8; r++) {
        int row = rowBase + r;
        float4 v = make_float4(0.f, 0.f, 0.f, 0.f);
        if (row < N_NODES) v = ((const float4*)x)[(size_t)row * 32 + lane];
        Xs[(warp * 8 + r) * 32 + lane] = v;
    }
    __syncthreads();

    unsigned long long acc2[8][4];
#pragma unroll
    for (int r = 0; r < 8; r++)
#pragma unroll
        for (int c = 0; c < 4; c++) acc2[r][c] = 0ull;

    for (int k4 = 0; k4 < 32; k4++) {
        unsigned long long xa[8], xb[8];
#pragma unroll
        for (int r = 0; r < 8; r++) {
            float4 xv = Xs[(warp * 8 + r) * 32 + k4];
            xa[r] = pack2(xv.x, xv.y);
            xb[r] = pack2(xv.z, xv.w);
        }
#pragma unroll
        for (int c = 0; c < 4; c++) {
            float4 wv = Ws[k4 * WS_PITCH + c * 32 + lane];
            unsigned long long wa = pack2(wv.x, wv.y);
            unsigned long long wb = pack2(wv.z, wv.w);
#pragma unroll
            for (int r = 0; r < 8; r++) {
                fma2(acc2[r][c], xa[r], wa);
                fma2(acc2[r][c], xb[r], wb);
            }
        }
    }

    float bv[4], sv[4], biv[4];
#pragma unroll
    for (int c = 0; c < 4; c++) {
        bv[c]  = __ldg(b + c * 32 + lane);
        sv[c]  = __ldg(scale + c * 32 + lane);
        biv[c] = __ldg(bias + c * 32 + lane);
    }

#pragma unroll
    for (int r = 0; r < 8; r++) {
        int row = rowBase + r;
        if (row >= N_NODES) break;
        float v[4];
#pragma unroll
        for (int c = 0; c < 4; c++) {
            float2 p = unpack2(acc2[r][c]);
            v[c] = p.x + p.y + bv[c];
        }
        float s = v[0] + v[1] + v[2] + v[3];
#pragma unroll
        for (int o = 16; o; o >>= 1) s += __shfl_xor_sync(FULL, s, o);
        float mu = s * (1.0f / 128.0f);
        float q = 0.f;
#pragma unroll
        for (int c = 0; c < 4; c++) {
            float d = v[c] - mu;
            q += d * d;
        }
#pragma unroll
        for (int o = 16; o; o >>= 1) q += __shfl_xor_sync(FULL, q, o);
        float rstd = rsqrtf(q * (1.0f / 128.0f) + 1e-5f);
        size_t base = (size_t)row * DIM;
#pragma unroll
        for (int c = 0; c < 4; c++) {
            h_out[base + c * 32 + lane] = __float2half_rn(v[c]);
            float t = fmaf((v[c] - mu) * rstd, sv[c], biv[c]);
            t_out[base + c * 32 + lane] = __float2half_rn(fmaxf(t, 0.0f));
        }
    }
}

// ---- CSR aggregation, MLP-12 chunked gathers + tail -----------------------
#define CHUNK 12
template <bool FUSE_LN>
__global__ void agg_kernel(const __half* __restrict__ t,
                           const __half* __restrict__ hres,
                           const float* __restrict__ scale,
                           const float* __restrict__ bias,
                           void* __restrict__ outp) {
    int warp = threadIdx.x >> 5;
    int lane = threadIdx.x & 31;
    int row = blockIdx.x * 8 + warp;
    if (row >= N_NODES) return;

    int beg = g_off[row], end = g_off[row + 1];
    float4 acc = make_float4(0.f, 0.f, 0.f, 0.f);

    int i = beg;
    for (; i + CHUNK <= end; i += CHUNK) {
        int2 eI[CHUNK];
#pragma unroll
        for (int j = 0; j < CHUNK; j++)
            eI[j] = __ldg(g_edge + i + j);     // warp-uniform 8B broadcast
        uint2 rv[CHUNK];
#pragma unroll
        for (int j = 0; j < CHUNK; j++)
            rv[j] = ((const uint2*)(t + (size_t)eI[j].x * DIM))[lane];
#pragma unroll
        for (int j = 0; j < CHUNK; j++) {
            float w = __int_as_float(eI[j].y);
            float2 f0 = __half22float2(*(const __half2*)&rv[j].x);
            float2 f1 = __half22float2(*(const __half2*)&rv[j].y);
            acc.x = fmaf(w, f0.x, acc.x);
            acc.y = fmaf(w, f0.y, acc.y);
            acc.z = fmaf(w, f1.x, acc.z);
            acc.w = fmaf(w, f1.y, acc.w);
        }
    }
    for (; i < end; i++) {
        int2 e = __ldg(g_edge + i);
        float w = __int_as_float(e.y);
        uint2 rv = ((const uint2*)(t + (size_t)e.x * DIM))[lane];
        float2 f0 = __half22float2(*(const __half2*)&rv.x);
        float2 f1 = __half22float2(*(const __half2*)&rv.y);
        acc.x = fmaf(w, f0.x, acc.x);
        acc.y = fmaf(w, f0.y, acc.y);
        acc.z = fmaf(w, f1.x, acc.z);
        acc.w = fmaf(w, f1.y, acc.w);
    }

    size_t base = (size_t)row * DIM;
    if (FUSE_LN) {
        uint2 hv = ((const uint2*)(hres + base))[lane];
        float2 h0 = __half22float2(*(const __half2*)&hv.x);
        float2 h1 = __half22float2(*(const __half2*)&hv.y);
        acc.x += h0.x; acc.y += h0.y; acc.z += h1.x; acc.w += h1.y;
        float s = acc.x + acc.y + acc.z + acc.w;
#pragma unroll
        for (int o2 = 16; o2; o2 >>= 1) s += __shfl_xor_sync(FULL, s, o2);
        float mu = s * (1.0f / 128.0f);
        float dx = acc.x - mu, dy = acc.y - mu, dz = acc.z - mu, dw = acc.w - mu;
        float q = dx * dx + dy * dy + dz * dz + dw * dw;
#pragma unroll
        for (int o2 = 16; o2; o2 >>= 1) q += __shfl_xor_sync(FULL, q, o2);
        float rstd = rsqrtf(q * (1.0f / 128.0f) + 1e-5f);
        float4 sc = ((const float4*)scale)[lane];
        float4 bi = ((const float4*)bias)[lane];
        float rx = fmaxf(fmaf(dx * rstd, sc.x, bi.x), 0.0f);
        float ry = fmaxf(fmaf(dy * rstd, sc.y, bi.y), 0.0f);
        float rz = fmaxf(fmaf(dz * rstd, sc.z, bi.z), 0.0f);
        float rw = fmaxf(fmaf(dw * rstd, sc.w, bi.w), 0.0f);
        uint2 st;
        *(__half2*)&st.x = __floats2half2_rn(rx, ry);
        *(__half2*)&st.y = __floats2half2_rn(rz, rw);
        ((uint2*)((__half*)outp + base))[lane] = st;
    } else {
        ((float4*)((float*)outp + base))[lane] = acc;
    }
}

extern "C" void kernel_launch(void* const* d_in, const int* in_sizes, int n_in,
                              void* d_out, int out_size) {
    const float* x = nullptr;
    const int*   ei_raw = nullptr;
    const float* ef = nullptr;
    const float* lin_w = nullptr;
    const float* lin_b = nullptr;
    const float* ln_scale = nullptr;
    const float* ln_bias = nullptr;
    for (int i = 0; i < n_in; i++) {
        switch (in_sizes[i]) {
            case N_NODES * DIM: x      = (const float*)d_in[i]; break;
            case 2 * E_EDGES:   ei_raw = (const int*)d_in[i];   break;
            case E_EDGES:       ef     = (const float*)d_in[i]; break;
            case DIM * DIM:     lin_w  = (const float*)d_in[i]; break;
            case DIM:           lin_b  = (const float*)d_in[i]; break;
            case 2 * DIM:
                if (!ln_scale) ln_scale = (const float*)d_in[i];
                else           ln_bias  = (const float*)d_in[i];
                break;
            default: break;
        }
    }
    float* out = (float*)d_out;

    __half *h, *t, *t2;
    cudaGetSymbolAddress((void**)&h,  g_h);
    cudaGetSymbolAddress((void**)&t,  g_t);
    cudaGetSymbolAddress((void**)&t2, g_t2);

    const int EDGE_BLKS = (E_EDGES + 255) / 256;
    const int NODE_BLKS = (N_NODES + 255) / 256;
    const int ROWS_GRID = (N_NODES + 7) / 8;
    const int GEMM_GRID = (N_NODES + 63) / 64;
    const int GEMM_SMEM = (32 * WS_PITCH + 8 * 8 * 32) * sizeof(float4);

    static cudaStream_t s_side = nullptr;
    static cudaEvent_t  ev_fork = nullptr, ev_join = nullptr;
    static bool init_done = false;
    if (!init_done) {
        cudaFuncSetAttribute(gemm_ln_kernel,
                             cudaFuncAttributeMaxDynamicSharedMemorySize,
                             GEMM_SMEM);
        if (cudaStreamCreateWithFlags(&s_side, cudaStreamNonBlocking) !=
            cudaSuccess) s_side = nullptr;
        if (s_side) {
            cudaEventCreateWithFlags(&ev_fork, cudaEventDisableTiming);
            cudaEventCreateWithFlags(&ev_join, cudaEventDisableTiming);
        }
        init_done = true;
    }

    if (s_side) {
        // fork: GEMM+LN0 on side stream, CSR build on main stream
        cudaEventRecord(ev_fork, 0);
        cudaStreamWaitEvent(s_side, ev_fork, 0);
        gemm_ln_kernel<<<GEMM_GRID, 256, GEMM_SMEM, s_side>>>(
            x, lin_w, lin_b, ln_scale, ln_bias, h, t);
        cudaEventRecord(ev_join, s_side);

        zero_detect_kernel<<<NODE_BLKS, 256>>>(ei_raw);
        hist_kernel<<<EDGE_BLKS, 256>>>(ei_raw);
        block_sum_kernel<<<SCAN_BLOCKS, 1024>>>();
        scan_apply_kernel<<<SCAN_BLOCKS, 1024>>>();
        fill_kernel<<<EDGE_BLKS, 256>>>(ei_raw, ef);

        cudaStreamWaitEvent(0, ev_join, 0);   // join before agg0
    } else {
        zero_detect_kernel<<<NODE_BLKS, 256>>>(ei_raw);
        hist_kernel<<<EDGE_BLKS, 256>>>(ei_raw);
        block_sum_kernel<<<SCAN_BLOCKS, 1024>>>();
        scan_apply_kernel<<<SCAN_BLOCKS, 1024>>>();
        fill_kernel<<<EDGE_BLKS, 256>>>(ei_raw, ef);
        gemm_ln_kernel<<<GEMM_GRID, 256, GEMM_SMEM>>>(
            x, lin_w, lin_b, ln_scale, ln_bias, h, t);
    }

    // ---- layer 0 agg + residual + LN1 + ReLU -> t2 (fp16) ----
    agg_kernel<true><<<ROWS_GRID, 256>>>(t, h, ln_scale + DIM, ln_bias + DIM,
                                         (void*)t2);

    // ---- layer 1 agg -> out (fp32) ----
    agg_kernel<false><<<ROWS_GRID, 256>>>(t2, nullptr, nullptr, nullptr,
                                          (void*)out);
}